// round 15
// baseline (speedup 1.0000x reference)
#include <cuda_runtime.h>
#include <math.h>

#define Nx   256
#define BN   2048      // 8*256

// ---------------- scratch ----------------
__device__ float g_A [BN*128];
__device__ float g_Bm[BN*128];
__device__ float g_as[BN];
__device__ float g_bs[BN];
__device__ float g_S [BN*128];
__device__ float g_c [BN];
__device__ float g_M [128*128];
__device__ float g_vb[128];
__device__ unsigned g_bar[2];    // monotonic barrier counters (never reset)

typedef unsigned long long u64;

__device__ __forceinline__ u64 dup2(float a) {
    u64 r; unsigned au = __float_as_uint(a);
    asm("mov.b64 %0, {%1, %1};" : "=l"(r) : "r"(au));
    return r;
}
__device__ __forceinline__ u64 add2v(u64 a, u64 b) {
    u64 r; asm("add.rn.f32x2 %0, %1, %2;" : "=l"(r) : "l"(a), "l"(b));
    return r;
}
__device__ __forceinline__ u64 fma2v(u64 a, u64 b, u64 c) {
    u64 r; asm("fma.rn.f32x2 %0, %1, %2, %3;" : "=l"(r) : "l"(a), "l"(b), "l"(c));
    return r;
}
__device__ __forceinline__ void fma2a(u64& acc, u64 a, u64 b) {
    asm("fma.rn.f32x2 %0, %1, %2, %0;" : "+l"(acc) : "l"(a), "l"(b));
}
__device__ __forceinline__ float2 unpk(u64 v) {
    unsigned lo, hi;
    asm("mov.b64 {%0, %1}, %2;" : "=r"(lo), "=r"(hi) : "l"(v));
    return make_float2(__uint_as_float(lo), __uint_as_float(hi));
}
__device__ __forceinline__ u64 pack2(float x, float y) {
    u64 r;
    asm("mov.b64 %0, {%1, %2};" : "=l"(r)
        : "r"(__float_as_uint(x)), "r"(__float_as_uint(y)));
    return r;
}
__device__ __forceinline__ u64 relu2(u64 v) {
    float2 f = unpk(v);
    return pack2(fmaxf(f.x, 0.f), fmaxf(f.y, 0.f));
}

// device-wide barrier: all 128 blocks co-resident (1/SM, 128<=148).
// Monotonic counter -> safe across graph replays without reset.
__device__ __forceinline__ void grid_barrier(int which) {
    __syncthreads();
    __threadfence();                       // release (flushes, CCTL.IVALL)
    __shared__ unsigned s_go;
    if (threadIdx.x == 0) {
        unsigned old = atomicAdd(&g_bar[which], 1u);
        unsigned target = old - (old & 127u) + 128u;
        while ((int)(atomicAdd(&g_bar[which], 0u) - target) < 0) { }
        s_go = 1u;
    }
    __syncthreads();
    __threadfence();                       // acquire
    (void)s_go;
}

#define FUSED_SMEM ((32768 + 16384 + 4096 + 2048 + 256 + 16) * 4)   // 222272B

__global__ void __launch_bounds__(512) k_fused(
    const float* __restrict__ h,    const int*   __restrict__ adj,
    const float* __restrict__ dist, const float* __restrict__ Wm1,
    const float* __restrict__ bm1,  const float* __restrict__ Wm2,
    const float* __restrict__ bm2,  const float* __restrict__ Wa,
    const float* __restrict__ ba,   const float* __restrict__ Wu,
    const float* __restrict__ bu,   float* __restrict__ out)
{
    extern __shared__ float sm[];
    const int bid  = blockIdx.x;      // 0..127
    const int t    = threadIdx.x;     // 0..511
    const int lane = t & 31, wrp = t >> 5;

    // ===================================================================
    // PHASE A: g_A/g_Bm (16 h-rows per block), g_M row, dots, vb
    // smem: Ws 32768 fl | As 2048 fl | scr 1024 fl
    // ===================================================================
    {
        float* Ws  = sm;               // Wm1[0:256][0:128] (128KB)
        float* As  = sm + 32768;       // h rows bid*16..+15
        float* scr = sm + 34816;       // reductions

        {   // fill W panel (8192 float4)
            const float4* src = (const float4*)Wm1;
            float4* d4 = (float4*)Ws;
#pragma unroll
            for (int n = 0; n < 16; n++) d4[t + n*512] = src[t + n*512];
            ((float4*)As)[t] = ((const float4*)(h + (size_t)bid*16*128))[t];
        }
        __syncthreads();

        // GEMM: thread (row = t>>5, c4 = (t&31)*4), K=128
        {
            const int row = wrp, c4 = lane*4;
            u64 a0 = 0ull, a1 = 0ull, b0 = 0ull, b1 = 0ull;
#pragma unroll 4
            for (int k0 = 0; k0 < 128; k0 += 4) {
                float4 a4 = *(const float4*)&As[row*128 + k0];
#pragma unroll
                for (int kk = 0; kk < 4; kk++) {
                    float av = (kk==0)?a4.x:(kk==1)?a4.y:(kk==2)?a4.z:a4.w;
                    u64 aa = dup2(av);
                    ulonglong2 wA = *(const ulonglong2*)&Ws[(k0+kk)*128 + c4];
                    ulonglong2 wB = *(const ulonglong2*)&Ws[(128+k0+kk)*128 + c4];
                    fma2a(a0, aa, wA.x); fma2a(a1, aa, wA.y);
                    fma2a(b0, aa, wB.x); fma2a(b1, aa, wB.y);
                }
            }
            const size_t rg = (size_t)(bid*16 + row)*128 + c4;
            float2 p, q;
            p = unpk(a0); q = unpk(a1);
            *(float4*)&g_A [rg] = make_float4(p.x, p.y, q.x, q.y);
            p = unpk(b0); q = unpk(b1);
            *(float4*)&g_Bm[rg] = make_float4(p.x, p.y, q.x, q.y);
        }

        // g_M row bid + (block 0) vb partials; 4 k-partials each
        {
            const int c = t & 127, kq = t >> 7;
            const float* wm2r = Wm2 + bid*128;
            float p0 = 0.f, p1 = 0.f;
            const int kb = kq*32;
#pragma unroll 4
            for (int k = 0; k < 32; k += 2) {
                p0 = fmaf(wm2r[kb+k],   Wu[(128+kb+k)*128 + c],   p0);
                p1 = fmaf(wm2r[kb+k+1], Wu[(128+kb+k+1)*128 + c], p1);
            }
            scr[kq*128 + c] = p0 + p1;
            if (bid == 0) {
                float v0 = 0.f, v1 = 0.f;
#pragma unroll 4
                for (int k = 0; k < 32; k += 2) {
                    v0 = fmaf(bm2[kb+k],   Wu[(128+kb+k)*128 + c],   v0);
                    v1 = fmaf(bm2[kb+k+1], Wu[(128+kb+k+1)*128 + c], v1);
                }
                scr[512 + kq*128 + c] = v0 + v1;
            }
        }

        // dots: warp wrp -> row bid*16 + wrp
        {
            const int row = bid*16 + wrp;
            float4 wa1 = *(const float4*)&Wa[lane*4];
            float4 wa2 = *(const float4*)&Wa[128 + lane*4];
            float4 hv  = *(const float4*)&h[(size_t)row*128 + lane*4];
            float sa = hv.x*wa1.x + hv.y*wa1.y + hv.z*wa1.z + hv.w*wa1.w;
            float sb = hv.x*wa2.x + hv.y*wa2.y + hv.z*wa2.z + hv.w*wa2.w;
#pragma unroll
            for (int o = 16; o; o >>= 1) {
                sa += __shfl_xor_sync(0xffffffffu, sa, o);
                sb += __shfl_xor_sync(0xffffffffu, sb, o);
            }
            if (lane == 0) { g_as[row] = sa; g_bs[row] = sb; }
        }
        __syncthreads();
        if (t < 128) {
            g_M[bid*128 + t] = scr[t] + scr[128+t] + scr[256+t] + scr[384+t];
            if (bid == 0)
                g_vb[t] = bu[t] + scr[512+t] + scr[640+t] + scr[768+t] + scr[896+t];
        }
    }

    grid_barrier(0);

    // ===================================================================
    // PHASE B: compacted pair (R14): bid -> (i-tile, batch)
    // smem: Bsh 32768 | recsh 16384 | jsh 4096 | Ash 2048 | bssh 256 | nnz
    // ===================================================================
    {
        float*      Bsh   = sm;
        ulonglong2* recsh = (ulonglong2*)(sm + 32768);
        int*        jsh   = (int*)(sm + 32768 + 16384);
        float*      Ash   = sm + 32768 + 16384 + 4096;
        float*      bssh  = Ash + 2048;
        int*        nnzsh = (int*)(bssh + 256);

        const int b  = bid >> 4;
        const int i0 = (bid & 15) * 16;

        {
            const float4* src = (const float4*)(g_Bm + (size_t)b*Nx*128);
            float4* d4 = (float4*)Bsh;
#pragma unroll
            for (int k = 0; k < 16; k++) d4[t + k*512] = src[t + k*512];
        }
#pragma unroll
        for (int k = 0; k < 4; k++) {
            int idx = t + k*512;
            Ash[idx] = g_A[(size_t)(b*Nx + i0)*128 + idx] + bm1[idx & 127];
        }
        if (t < 256) bssh[t] = g_bs[b*Nx + t];
        __syncthreads();

        // phase 1: softmax + ballot compaction (warp wrp -> i)
        {
            const float wa_d = Wa[256];
            const int ig = b*Nx + i0 + wrp;
            const float a_i = g_as[ig] + ba[0];
            float l[8], dv[8]; int mk[8];
#pragma unroll
            for (int jj = 0; jj < 8; jj++) {
                int j = jj*32 + lane;
                float d = dist[(size_t)ig*Nx + j];
                int   m = adj [(size_t)ig*Nx + j];
                float x = fmaf(d, wa_d, a_i + bssh[j]);
                x = (x >= 0.f) ? x : 0.2f * x;
                l[jj] = m ? x : -1e9f;
                dv[jj] = d; mk[jj] = m;
            }
            float mx = l[0];
#pragma unroll
            for (int jj = 1; jj < 8; jj++) mx = fmaxf(mx, l[jj]);
#pragma unroll
            for (int o = 16; o; o >>= 1) mx = fmaxf(mx, __shfl_xor_sync(0xffffffffu, mx, o));
            float sum = 0.f, cs = 0.f;
#pragma unroll
            for (int jj = 0; jj < 8; jj++) {
                float e = expf(l[jj] - mx);
                l[jj] = e; sum += e;
                cs += mk[jj] ? e : 0.f;
            }
#pragma unroll
            for (int o = 16; o; o >>= 1) {
                sum += __shfl_xor_sync(0xffffffffu, sum, o);
                cs  += __shfl_xor_sync(0xffffffffu, cs,  o);
            }
            const float inv = 1.f / sum;
            int nbase = 0;
#pragma unroll
            for (int jj = 0; jj < 8; jj++) {
                unsigned bal = __ballot_sync(0xffffffffu, mk[jj] != 0);
                if (mk[jj]) {
                    int pos = nbase + __popc(bal & ((1u << lane) - 1u));
                    ulonglong2 rec;
                    rec.x = dup2(dv[jj]);
                    rec.y = dup2(l[jj] * inv);
                    recsh[wrp*256 + pos] = rec;
                    jsh  [wrp*256 + pos] = jj*32 + lane;
                }
                nbase += __popc(bal);
            }
            if (lane == 0) { nnzsh[wrp] = nbase; g_c[ig] = cs * inv; }
        }
        __syncthreads();

        // phase 2: compacted lists
        const int cp = t & 63, q = t >> 6;
        const u64 wd2 = *(const u64*)&Wm1[256*128 + cp*2];
        u64 acc2[16];
#pragma unroll
        for (int i = 0; i < 16; i++) acc2[i] = 0ull;

#pragma unroll
        for (int i = 0; i < 16; i++) {
            const u64 av = *(const u64*)&Ash[i*128 + cp*2];
            const int n = nnzsh[i];
            const ulonglong2* rp = recsh + i*256;
            const int*        jp = jsh   + i*256;
#pragma unroll 2
            for (int s = q; s < n; s += 8) {
                int j = jp[s];
                ulonglong2 rec = rp[s];
                u64 b2 = *(const u64*)&Bsh[j*128 + cp*2];
                u64 x = fma2v(rec.x, wd2, add2v(av, b2));
                acc2[i] = fma2v(rec.y, relu2(x), acc2[i]);
            }
        }
        __syncthreads();

        u64* part = (u64*)recsh;
#pragma unroll
        for (int i = 0; i < 16; i++) part[(i*8 + q)*64 + cp] = acc2[i];
        __syncthreads();
#pragma unroll
        for (int rep = 0; rep < 2; rep++) {
            int it = t + rep*512;
            int i = it >> 6, cpp = it & 63;
            float2 s = make_float2(0.f, 0.f);
#pragma unroll
            for (int qq = 0; qq < 8; qq++) {
                float2 v = unpk(part[(i*8 + qq)*64 + cpp]);
                s.x += v.x; s.y += v.y;
            }
            *(float2*)&g_S[(size_t)(b*Nx + i0 + i)*128 + cpp*2] = s;
        }
    }

    grid_barrier(1);

    // ===================================================================
    // PHASE C: out = relu([h|S] @ [Wu_top;M] + c*vb)
    // bid: row0 = (bid&63)*32, col0 = (bid>>6)*64; 512 thr, 1x4 micro
    // ===================================================================
    {
        float* As2 = sm;               // [32][36] transposed A
        float* Ws2 = sm + 1152;        // [32][68]
        const int row0 = (bid & 63) * 32;
        const int col0 = (bid >> 6) * 64;
        const int row = t >> 4, tx = t & 15;

        float acc[4] = {0.f, 0.f, 0.f, 0.f};

        for (int k0 = 0; k0 < 256; k0 += 32) {
            __syncthreads();
            if (t < 256) {
                int r  = t >> 3;
                int kq = (t & 7) * 4;
                int kg = k0 + kq;
                const float* src = (kg < 128)
                    ? &h  [(size_t)(row0 + r)*128 + kg]
                    : &g_S[(size_t)(row0 + r)*128 + kg - 128];
                float4 v = *(const float4*)src;
                As2[(kq+0)*36 + r] = v.x; As2[(kq+1)*36 + r] = v.y;
                As2[(kq+2)*36 + r] = v.z; As2[(kq+3)*36 + r] = v.w;
            }
            {
                int wk = t >> 4, wn = (t & 15) * 4;
                int kg = k0 + wk;
                const float* src = (kg < 128)
                    ? &Wu [(size_t)kg*128 + col0 + wn]
                    : &g_M[(size_t)(kg - 128)*128 + col0 + wn];
                *(float4*)&Ws2[wk*68 + wn] = *(const float4*)src;
            }
            __syncthreads();
#pragma unroll
            for (int kk = 0; kk < 32; kk++) {
                float a = As2[kk*36 + row];
                float4 b4 = *(const float4*)&Ws2[kk*68 + tx*4];
                acc[0] = fmaf(a, b4.x, acc[0]);
                acc[1] = fmaf(a, b4.y, acc[1]);
                acc[2] = fmaf(a, b4.z, acc[2]);
                acc[3] = fmaf(a, b4.w, acc[3]);
            }
        }

        const int rowg = row0 + row;
        float cr = g_c[rowg];
        float4 vb4 = *(const float4*)&g_vb[col0 + tx*4];
        float4 o;
        o.x = fmaxf(fmaf(cr, vb4.x, acc[0]), 0.f);
        o.y = fmaxf(fmaf(cr, vb4.y, acc[1]), 0.f);
        o.z = fmaxf(fmaf(cr, vb4.z, acc[2]), 0.f);
        o.w = fmaxf(fmaf(cr, vb4.w, acc[3]), 0.f);
        *(float4*)&out[(size_t)rowg*128 + col0 + tx*4] = o;
    }
}

// =======================================================================
extern "C" void kernel_launch(void* const* d_in, const int* in_sizes, int n_in,
                              void* d_out, int out_size)
{
    const float* h    = (const float*)d_in[0];
    const int*   adj  = (const int*)  d_in[1];
    const float* dist = (const float*)d_in[2];
    const float* Wm1  = (const float*)d_in[3];
    const float* bm1  = (const float*)d_in[4];
    const float* Wm2  = (const float*)d_in[5];
    const float* bm2  = (const float*)d_in[6];
    const float* Wa   = (const float*)d_in[7];
    const float* ba   = (const float*)d_in[8];
    const float* Wu   = (const float*)d_in[9];
    const float* bu   = (const float*)d_in[10];
    float* out = (float*)d_out;

    cudaFuncSetAttribute(k_fused, cudaFuncAttributeMaxDynamicSharedMemorySize,
                         FUSED_SMEM);

    k_fused<<<128, 512, FUSED_SMEM>>>(h, adj, dist, Wm1, bm1, Wm2, bm2,
                                      Wa, ba, Wu, bu, out);
}

// round 16
// speedup vs baseline: 1.3719x; 1.3719x over previous
#include <cuda_runtime.h>
#include <math.h>

#define Nx   256
#define BN   2048      // 8*256

// ---------------- scratch ----------------
__device__ float g_A [BN*128];   // h @ Wm1[0:128]
__device__ float g_Bm[BN*128];   // h @ Wm1[128:256]
__device__ float g_as[BN];
__device__ float g_bs[BN];
__device__ float g_S [BN*128];   // sum_j w_ij * relu(pre_ij)
__device__ float g_c [BN];       // sum_j w_ij
__device__ float g_M [128*128];  // Wm2 @ Wu_bot
__device__ float g_vb[128];      // bm2 @ Wu_bot + bu

typedef unsigned long long u64;

__device__ __forceinline__ u64 dup2(float a) {
    u64 r; unsigned au = __float_as_uint(a);
    asm("mov.b64 %0, {%1, %1};" : "=l"(r) : "r"(au));
    return r;
}
__device__ __forceinline__ u64 add2v(u64 a, u64 b) {
    u64 r; asm("add.rn.f32x2 %0, %1, %2;" : "=l"(r) : "l"(a), "l"(b));
    return r;
}
__device__ __forceinline__ u64 fma2v(u64 a, u64 b, u64 c) {
    u64 r; asm("fma.rn.f32x2 %0, %1, %2, %3;" : "=l"(r) : "l"(a), "l"(b), "l"(c));
    return r;
}
__device__ __forceinline__ float2 unpk(u64 v) {
    unsigned lo, hi;
    asm("mov.b64 {%0, %1}, %2;" : "=r"(lo), "=r"(hi) : "l"(v));
    return make_float2(__uint_as_float(lo), __uint_as_float(hi));
}
__device__ __forceinline__ u64 pack2(float x, float y) {
    u64 r;
    asm("mov.b64 %0, {%1, %2};" : "=l"(r)
        : "r"(__float_as_uint(x)), "r"(__float_as_uint(y)));
    return r;
}
__device__ __forceinline__ u64 relu2(u64 v) {
    float2 f = unpk(v);
    return pack2(fmaxf(f.x, 0.f), fmaxf(f.y, 0.f));
}

// =======================================================================
// Stage 1 (R2-proven, verbatim): grid 141, block 256
// =======================================================================
__global__ void __launch_bounds__(256) k_stage1(
    const float* __restrict__ h,   const float* __restrict__ Wm1,
    const float* __restrict__ Wa,  const float* __restrict__ Wm2,
    const float* __restrict__ bm2, const float* __restrict__ Wu,
    const float* __restrict__ bu)
{
    const int bid = blockIdx.x;
    const int t   = threadIdx.x;

    if (bid < 132) {
        __shared__ float As[32][68];
        __shared__ float Ws[32][68];
        const float *A, *W;
        float* dst;
        int row0, col0;
        if (bid < 128) {
            int mt = bid >> 2, nt = bid & 3;
            row0 = mt * 64;
            A = h;
            W = Wm1 + (nt >= 2 ? 128*128 : 0);
            col0 = (nt & 1) * 64;
            dst = (nt >= 2) ? g_Bm : g_A;
        } else {
            int bb = bid - 128;
            row0 = (bb >> 1) * 64;
            A = Wm2;
            W = Wu + 128*128;
            col0 = (bb & 1) * 64;
            dst = g_M;
        }
        const int ty = t >> 4, tx = t & 15;
        float acc[4][4];
#pragma unroll
        for (int r = 0; r < 4; r++)
#pragma unroll
            for (int c = 0; c < 4; c++) acc[r][c] = 0.f;

        for (int k0 = 0; k0 < 128; k0 += 32) {
#pragma unroll
            for (int n = 0; n < 2; n++) {
                int l  = t + n*256;
                int r  = l >> 3;
                int kq = (l & 7) * 4;
                float4 v = *(const float4*)&A[(row0 + r)*128 + k0 + kq];
                As[kq+0][r] = v.x; As[kq+1][r] = v.y;
                As[kq+2][r] = v.z; As[kq+3][r] = v.w;
            }
#pragma unroll
            for (int n = 0; n < 2; n++) {
                int l  = t + n*256;
                int wk = l >> 4;
                int wn = (l & 15) * 4;
                *(float4*)&Ws[wk][wn] =
                    *(const float4*)&W[(k0 + wk)*128 + col0 + wn];
            }
            __syncthreads();
#pragma unroll
            for (int kk = 0; kk < 32; kk++) {
                float4 a4 = *(const float4*)&As[kk][ty*4];
                float4 b4 = *(const float4*)&Ws[kk][tx*4];
                acc[0][0] = fmaf(a4.x, b4.x, acc[0][0]);
                acc[0][1] = fmaf(a4.x, b4.y, acc[0][1]);
                acc[0][2] = fmaf(a4.x, b4.z, acc[0][2]);
                acc[0][3] = fmaf(a4.x, b4.w, acc[0][3]);
                acc[1][0] = fmaf(a4.y, b4.x, acc[1][0]);
                acc[1][1] = fmaf(a4.y, b4.y, acc[1][1]);
                acc[1][2] = fmaf(a4.y, b4.z, acc[1][2]);
                acc[1][3] = fmaf(a4.y, b4.w, acc[1][3]);
                acc[2][0] = fmaf(a4.z, b4.x, acc[2][0]);
                acc[2][1] = fmaf(a4.z, b4.y, acc[2][1]);
                acc[2][2] = fmaf(a4.z, b4.z, acc[2][2]);
                acc[2][3] = fmaf(a4.z, b4.w, acc[2][3]);
                acc[3][0] = fmaf(a4.w, b4.x, acc[3][0]);
                acc[3][1] = fmaf(a4.w, b4.y, acc[3][1]);
                acc[3][2] = fmaf(a4.w, b4.z, acc[3][2]);
                acc[3][3] = fmaf(a4.w, b4.w, acc[3][3]);
            }
            __syncthreads();
        }
#pragma unroll
        for (int r = 0; r < 4; r++)
            *(float4*)&dst[(row0 + ty*4 + r)*128 + col0 + tx*4] =
                make_float4(acc[r][0], acc[r][1], acc[r][2], acc[r][3]);

    } else if (bid < 140) {
        __shared__ __align__(16) float was[272];
        for (int k = t; k < 257; k += 256) was[k] = Wa[k];
        __syncthreads();
        const int wrp = t >> 5, lane = t & 31;
        const int rowbase = (bid - 132) * 256 + wrp * 32;
        float4 wa1 = *(const float4*)&was[lane*4];
        float4 wa2 = *(const float4*)&was[128 + lane*4];
        for (int rr = 0; rr < 32; rr++) {
            int row = rowbase + rr;
            float4 hv = *(const float4*)&h[row*128 + lane*4];
            float sa = hv.x*wa1.x + hv.y*wa1.y + hv.z*wa1.z + hv.w*wa1.w;
            float sb = hv.x*wa2.x + hv.y*wa2.y + hv.z*wa2.z + hv.w*wa2.w;
#pragma unroll
            for (int o = 16; o; o >>= 1) {
                sa += __shfl_xor_sync(0xffffffffu, sa, o);
                sb += __shfl_xor_sync(0xffffffffu, sb, o);
            }
            if (lane == 0) { g_as[row] = sa; g_bs[row] = sb; }
        }
    } else {
        if (t < 128) {
            float acc = bu[t];
#pragma unroll 8
            for (int k = 0; k < 128; k++)
                acc = fmaf(bm2[k], Wu[(128 + k)*128 + t], acc);
            g_vb[t] = acc;
        }
    }
}

// =======================================================================
// k_pair: compaction + 4-channels/thread + 8-i blocks
// grid (32,8), block 512 (16 warps), dyn smem 177184
//  smem: Bsh [256][128] 128KB | recsh [8][256] u64x2 32KB |
//        jsh [8][256] 8KB | Ash [8][128] 4KB | bssh 1KB | nnz
//  phase1: warps 0..7 softmax+compact (i = i0+wrp); warps 8..15 fill Bsh
//  phase2: thread (cp=lane -> 4ch, q=warp -> j-stride 16), i = 0..7
// =======================================================================
#define PAIR_SMEM ((32768 + 8192 + 2048 + 1024 + 256 + 8) * 4)

__global__ void __launch_bounds__(512, 1) k_pair(
    const float* __restrict__ dist, const int* __restrict__ adj,
    const float* __restrict__ Wm1,  const float* __restrict__ bm1,
    const float* __restrict__ Wa,   const float* __restrict__ ba)
{
    extern __shared__ float sm[];
    float*      Bsh   = sm;                              // [256][128]
    ulonglong2* recsh = (ulonglong2*)(sm + 32768);       // [8][256] {dd,ww}
    int*        jsh   = (int*)(sm + 32768 + 8192);       // [8][256]
    float*      Ash   = sm + 32768 + 8192 + 2048;        // [8][128] A+bm1
    float*      bssh  = Ash + 1024;                      // 256
    int*        nnzsh = (int*)(bssh + 256);              // 8

    const int t = threadIdx.x;
    const int b = blockIdx.y, i0 = blockIdx.x * 8;
    const int lane = t & 31, wrp = t >> 5;

    // ---- small fills (all threads)
    if (t < 256) bssh[t] = g_bs[b*Nx + t];
#pragma unroll
    for (int k = 0; k < 2; k++) {
        int idx = t + k*512;
        if (idx < 1024)
            Ash[idx] = g_A[(size_t)(b*Nx + i0)*128 + idx] + bm1[idx & 127];
    }
    __syncthreads();

    // ---- phase 1 (warps 0..7) || Bsh fill (warps 8..15)
    if (wrp < 8) {
        const float wa_d = Wa[256];
        const int ig = b*Nx + i0 + wrp;
        const float a_i = g_as[ig] + ba[0];
        float l[8], dv[8]; int mk[8];
#pragma unroll
        for (int jj = 0; jj < 8; jj++) {
            int j = jj*32 + lane;
            float d = dist[(size_t)ig*Nx + j];
            int   m = adj [(size_t)ig*Nx + j];
            float x = fmaf(d, wa_d, a_i + bssh[j]);
            x = (x >= 0.f) ? x : 0.2f * x;
            l[jj] = m ? x : -1e9f;
            dv[jj] = d; mk[jj] = m;
        }
        float mx = l[0];
#pragma unroll
        for (int jj = 1; jj < 8; jj++) mx = fmaxf(mx, l[jj]);
#pragma unroll
        for (int o = 16; o; o >>= 1) mx = fmaxf(mx, __shfl_xor_sync(0xffffffffu, mx, o));
        float sum = 0.f, cs = 0.f;
#pragma unroll
        for (int jj = 0; jj < 8; jj++) {
            float e = expf(l[jj] - mx);
            l[jj] = e; sum += e;
            cs += mk[jj] ? e : 0.f;
        }
#pragma unroll
        for (int o = 16; o; o >>= 1) {
            sum += __shfl_xor_sync(0xffffffffu, sum, o);
            cs  += __shfl_xor_sync(0xffffffffu, cs,  o);
        }
        const float inv = 1.f / sum;
        int nbase = 0;
#pragma unroll
        for (int jj = 0; jj < 8; jj++) {
            unsigned bal = __ballot_sync(0xffffffffu, mk[jj] != 0);
            if (mk[jj]) {
                int pos = nbase + __popc(bal & ((1u << lane) - 1u));
                ulonglong2 rec;
                rec.x = dup2(dv[jj]);
                rec.y = dup2(l[jj] * inv);
                recsh[wrp*256 + pos] = rec;
                jsh  [wrp*256 + pos] = jj*32 + lane;
            }
            nbase += __popc(bal);
        }
        if (lane == 0) { nnzsh[wrp] = nbase; g_c[ig] = cs * inv; }
    } else {
        const float4* src = (const float4*)(g_Bm + (size_t)b*Nx*128);
        float4* d4 = (float4*)Bsh;
        const int tl = t - 256;           // 0..255
#pragma unroll
        for (int k = 0; k < 32; k++) d4[tl + k*256] = src[tl + k*256];
    }
    __syncthreads();

    // ---- phase 2: thread (cp 0..31 -> 4ch, q 0..15 -> j stride)
    const int cp = lane, q = wrp;
    const ulonglong2 wd4 = *(const ulonglong2*)&Wm1[256*128 + cp*4];
    ulonglong2 acc[8];
#pragma unroll
    for (int i = 0; i < 8; i++) { acc[i].x = 0ull; acc[i].y = 0ull; }

#pragma unroll
    for (int i = 0; i < 8; i++) {
        const ulonglong2 av = *(const ulonglong2*)&Ash[i*128 + cp*4];
        const int n = nnzsh[i];
        const ulonglong2* rp = recsh + i*256;
        const int*        jp = jsh   + i*256;
        for (int s = q; s < n; s += 16) {
            int j = jp[s];                    // bcast LDS.32
            ulonglong2 rec = rp[s];           // bcast LDS.128 {dd, ww}
            ulonglong2 b4 = *(const ulonglong2*)&Bsh[j*128 + cp*4];
            u64 x0 = fma2v(rec.x, wd4.x, add2v(av.x, b4.x));
            u64 x1 = fma2v(rec.x, wd4.y, add2v(av.y, b4.y));
            acc[i].x = fma2v(rec.y, relu2(x0), acc[i].x);
            acc[i].y = fma2v(rec.y, relu2(x1), acc[i].y);
        }
    }
    __syncthreads();   // Bsh/recsh/jsh reads done

    // ---- reduce over 16 q partials via overlay on Bsh (64KB)
    ulonglong2* part = (ulonglong2*)Bsh;   // [8][16][32]
#pragma unroll
    for (int i = 0; i < 8; i++)
        part[(i*16 + q)*32 + cp] = acc[i];
    __syncthreads();

    if (t < 256) {
        const int i = t >> 5, cpp = t & 31;
        u64 sx = 0ull, sy = 0ull;
#pragma unroll
        for (int qq = 0; qq < 16; qq++) {
            ulonglong2 v = part[(i*16 + qq)*32 + cpp];
            sx = add2v(sx, v.x); sy = add2v(sy, v.y);
        }
        float2 p = unpk(sx), r = unpk(sy);
        *(float4*)&g_S[(size_t)(b*Nx + i0 + i)*128 + cpp*4] =
            make_float4(p.x, p.y, r.x, r.y);
    }
}

// =======================================================================
// k_out (R2-proven, verbatim): out = relu( [h|S] @ [Wu_top;M] + c*vb )
// grid (64,2), block 256
// =======================================================================
__global__ void __launch_bounds__(256) k_out(
    const float* __restrict__ h, const float* __restrict__ Wu,
    float* __restrict__ out)
{
    __shared__ float As[32][36];
    __shared__ float Ws[32][68];
    const int t = threadIdx.x;
    const int row0 = blockIdx.x * 32, col0 = blockIdx.y * 64;
    const int ty = t >> 4, tx = t & 15;
    float acc[2][4];
#pragma unroll
    for (int r = 0; r < 2; r++)
#pragma unroll
        for (int c = 0; c < 4; c++) acc[r][c] = 0.f;

    for (int k0 = 0; k0 < 256; k0 += 32) {
        {
            int r  = t >> 3;
            int kq = (t & 7) * 4;
            int kg = k0 + kq;
            const float* src = (kg < 128) ? &h  [(row0 + r)*128 + kg]
                                          : &g_S[(row0 + r)*128 + kg - 128];
            float4 v = *(const float4*)src;
            As[kq+0][r] = v.x; As[kq+1][r] = v.y;
            As[kq+2][r] = v.z; As[kq+3][r] = v.w;
        }
#pragma unroll
        for (int n = 0; n < 2; n++) {
            int l  = t + n*256;
            int wk = l >> 4;
            int wn = (l & 15) * 4;
            int kg = k0 + wk;
            const float* src = (kg < 128) ? &Wu [kg*128 + col0 + wn]
                                          : &g_M[(kg - 128)*128 + col0 + wn];
            *(float4*)&Ws[wk][wn] = *(const float4*)src;
        }
        __syncthreads();
#pragma unroll
        for (int kk = 0; kk < 32; kk++) {
            float2 a2 = *(const float2*)&As[kk][ty*2];
            float4 b4 = *(const float4*)&Ws[kk][tx*4];
            acc[0][0] = fmaf(a2.x, b4.x, acc[0][0]);
            acc[0][1] = fmaf(a2.x, b4.y, acc[0][1]);
            acc[0][2] = fmaf(a2.x, b4.z, acc[0][2]);
            acc[0][3] = fmaf(a2.x, b4.w, acc[0][3]);
            acc[1][0] = fmaf(a2.y, b4.x, acc[1][0]);
            acc[1][1] = fmaf(a2.y, b4.y, acc[1][1]);
            acc[1][2] = fmaf(a2.y, b4.z, acc[1][2]);
            acc[1][3] = fmaf(a2.y, b4.w, acc[1][3]);
        }
        __syncthreads();
    }

    float4 vb4 = *(const float4*)&g_vb[col0 + tx*4];
#pragma unroll
    for (int r = 0; r < 2; r++) {
        int row = row0 + ty*2 + r;
        float cr = g_c[row];
        float4 v;
        v.x = fmaxf(fmaf(cr, vb4.x, acc[r][0]), 0.f);
        v.y = fmaxf(fmaf(cr, vb4.y, acc[r][1]), 0.f);
        v.z = fmaxf(fmaf(cr, vb4.z, acc[r][2]), 0.f);
        v.w = fmaxf(fmaf(cr, vb4.w, acc[r][3]), 0.f);
        *(float4*)&out[row*128 + col0 + tx*4] = v;
    }
}

// =======================================================================
extern "C" void kernel_launch(void* const* d_in, const int* in_sizes, int n_in,
                              void* d_out, int out_size)
{
    const float* h    = (const float*)d_in[0];
    const int*   adj  = (const int*)  d_in[1];
    const float* dist = (const float*)d_in[2];
    const float* Wm1  = (const float*)d_in[3];
    const float* bm1  = (const float*)d_in[4];
    const float* Wm2  = (const float*)d_in[5];
    const float* bm2  = (const float*)d_in[6];
    const float* Wa   = (const float*)d_in[7];
    const float* ba   = (const float*)d_in[8];
    const float* Wu   = (const float*)d_in[9];
    const float* bu   = (const float*)d_in[10];
    float* out = (float*)d_out;

    cudaFuncSetAttribute(k_pair, cudaFuncAttributeMaxDynamicSharedMemorySize,
                         PAIR_SMEM);

    k_stage1<<<141, 256>>>(h, Wm1, Wa, Wm2, bm2, Wu, bu);
    k_pair  <<<dim3(32, 8), 512, PAIR_SMEM>>>(dist, adj, Wm1, bm1, Wa, ba);
    k_out   <<<dim3(64, 2), 256>>>(h, Wu, out);
}